// round 16
// baseline (speedup 1.0000x reference)
#include <cuda_runtime.h>
#include <cuda_bf16.h>
#include <math.h>
#include <stdint.h>

// Problem constants
#define BATCH 4
#define TQN   9
#define TFR   8
#define HWN   1024
#define DIMN  256
#define NHN   8
#define DHN   32
#define MLPD  1024
#define NROWS    (BATCH*TQN*HWN)   // 36864
#define NROWS_SP (BATCH*TFR*HWN)   // 32768
#define SCALE 0.17677669529663687f

// ---------------- scratch ----------------------------------------------
__device__ __align__(16) float g_q [NROWS*DIMN];
__device__ __align__(16) float g_k [NROWS*DIMN];
__device__ __align__(16) float g_v [NROWS*DIMN];
__device__ __align__(16) float g_x [NROWS*DIMN];
__device__ __align__(16) float g_clsp[BATCH*8*DIMN];
__device__ __align__(16) __nv_bfloat16 g_xnh[NROWS*DIMN];
__device__ __align__(16) __nv_bfloat16 g_xnl[NROWS*DIMN];
__device__ __align__(16) __nv_bfloat16 g_oh [NROWS*DIMN];
__device__ __align__(16) __nv_bfloat16 g_ol [NROWS*DIMN];
__device__ __align__(16) __nv_bfloat16 g_hh [(long)NROWS*MLPD];
__device__ __align__(16) __nv_bfloat16 g_hl [(long)NROWS*MLPD];
__device__ __align__(16) __nv_bfloat16 g_wth[1048576];
__device__ __align__(16) __nv_bfloat16 g_wtl[1048576];

// ---------------- helpers ----------------------------------------------
__device__ __forceinline__ uint32_t s2u(const void* p) {
    uint32_t a;
    asm("{ .reg .u64 t; cvta.to.shared.u64 t, %1; cvt.u32.u64 %0, t; }" : "=r"(a) : "l"(p));
    return a;
}
__device__ __forceinline__ void ldsm4(uint32_t* r, uint32_t addr) {
    asm volatile("ldmatrix.sync.aligned.m8n8.x4.shared.b16 {%0,%1,%2,%3}, [%4];"
                 : "=r"(r[0]), "=r"(r[1]), "=r"(r[2]), "=r"(r[3]) : "r"(addr));
}
__device__ __forceinline__ void mma16816(float* d, const uint32_t* a, const uint32_t* b) {
    asm volatile("mma.sync.aligned.m16n8k16.row.col.f32.bf16.bf16.f32 "
                 "{%0,%1,%2,%3}, {%4,%5,%6,%7}, {%8,%9}, {%0,%1,%2,%3};"
                 : "+f"(d[0]), "+f"(d[1]), "+f"(d[2]), "+f"(d[3])
                 : "r"(a[0]), "r"(a[1]), "r"(a[2]), "r"(a[3]), "r"(b[0]), "r"(b[1]));
}
__device__ __forceinline__ void cpa16(uint32_t sm, const void* g) {
    asm volatile("cp.async.cg.shared.global [%0], [%1], 16;" :: "r"(sm), "l"(g));
}
__device__ __forceinline__ void split_bf16(float v, __nv_bfloat16& h, __nv_bfloat16& l) {
    h = __float2bfloat16(v);
    l = __float2bfloat16(v - __bfloat162float(h));
}
__device__ __forceinline__ uint32_t pack2(__nv_bfloat16 a, __nv_bfloat16 b) {
    return ((uint32_t)__bfloat16_as_ushort(b) << 16) | __bfloat16_as_ushort(a);
}

// ---------------- all-weights transpose + hi/lo split ------------------------
__global__ void wsplit_all(const float* s0, const float* s1, const float* s2, const float* s3,
                           const float* s4, const float* s5, const float* s6, const float* s7,
                           const float* s8, const float* s9,
                           __nv_bfloat16* __restrict__ Th, __nv_bfloat16* __restrict__ Tl)
{
    __shared__ float tile[32][33];
    int t = blockIdx.x;
    const float* W; long dst; int K, M, mtile, ktile;
    if (t < 512) {
        int j = t >> 6, wi = t & 63;
        K = 256; M = 256; mtile = wi & 7; ktile = wi >> 3;
        dst = (long)j * 65536;
        switch (j) {
            case 0: W = s0; break; case 1: W = s1; break; case 2: W = s2; break;
            case 3: W = s3; break; case 4: W = s4; break; case 5: W = s5; break;
            case 6: W = s6; break; default: W = s7; break;
        }
    } else if (t < 768) {
        int wi = t - 512;
        K = 256; M = 1024; mtile = wi & 31; ktile = wi >> 5;
        dst = 524288; W = s8;
    } else {
        int wi = t - 768;
        K = 1024; M = 256; mtile = wi & 7; ktile = wi >> 3;
        dst = 786432; W = s9;
    }
    int mb = mtile * 32, kb = ktile * 32;
    int tx = threadIdx.x, ty = threadIdx.y;
    #pragma unroll
    for (int i = 0; i < 32; i += 8)
        tile[ty + i][tx] = W[(long)(kb + ty + i) * M + mb + tx];
    __syncthreads();
    #pragma unroll
    for (int i = 0; i < 32; i += 8) {
        float v = tile[tx][ty + i];
        __nv_bfloat16 h, l; split_bf16(v, h, l);
        long o = dst + (long)(mb + ty + i) * K + kb + tx;
        Th[o] = h; Tl[o] = l;
    }
}

// ---------------- mma.sync bf16 split GEMM -----------------------------------
// R16: 128x64 tile (warp tile 64x16), BK=32, 2-stage cp.async — lower regs so
// 2 CTAs/SM actually fit (round-8's 128 tile used 130 regs -> 1 CTA/SM).
// Stage: A 16KB @ +0, B 8KB @ +16384; stage stride 24576; 2 stages = 48KB.
#define MMA_SMEM 49152

__global__ void __launch_bounds__(256, 2)
mmagemm(const __nv_bfloat16* __restrict__ Ah, const __nv_bfloat16* __restrict__ Al,
        const __nv_bfloat16* __restrict__ Wh, const __nv_bfloat16* __restrict__ Wl,
        const float* __restrict__ bias, const float* __restrict__ biasB,
        const float* __restrict__ biasC, const float* __restrict__ res,
        float* __restrict__ out, float* __restrict__ outB, float* __restrict__ outC,
        __nv_bfloat16* __restrict__ outh, __nv_bfloat16* __restrict__ outl,
        int M, int K, int mode, int remap)
{
    extern __shared__ __align__(1024) char smem[];
    uint32_t sb = s2u(smem);
    int tid = threadIdx.x, wid = tid >> 5, lane = tid & 31;
    int wm = (wid & 1) * 64;          // warp m offset (2 m-groups)
    int wn = (wid >> 1) * 16;         // warp n offset (4 n-groups of 16)

    long rowBase = (long)blockIdx.y * 128;
    int  colBase = blockIdx.x * 64;
    const __nv_bfloat16* Ahp = Ah + rowBase * K;
    const __nv_bfloat16* Alp = Al + rowBase * K;
    const __nv_bfloat16* Whp = Wh + (long)colBase * K;
    const __nv_bfloat16* Wlp = Wl + (long)colBase * K;

    float acc[4][2][4];
    #pragma unroll
    for (int i = 0; i < 4; i++)
        #pragma unroll
        for (int j = 0; j < 2; j++)
            #pragma unroll
            for (int tt = 0; tt < 4; tt++) acc[i][j][tt] = 0.f;

    int nchunk = K >> 5;

    // stage: 1536 16B slots; 0..1023 = A (128 rows), 1024..1535 = B (64 rows).
    auto stage = [&](int s, int kbase) {
        uint32_t base = sb + s * 24576;
        #pragma unroll
        for (int i = 0; i < 6; i++) {
            int slot = tid + i * 256;
            int isB = (slot >= 1024);
            int s2 = isB ? (slot - 1024) : slot;
            int row = s2 >> 3;
            int cch = s2 & 7;                  // 0-3 hi, 4-7 lo
            uint32_t off = row * 128 + cch * 16;
            uint32_t sw = off ^ ((off >> 3) & 0x70);
            long go = (long)row * K + kbase + (cch & 3) * 8;
            const __nv_bfloat16* src = isB
                ? ((cch < 4) ? Whp : Wlp) + go
                : ((cch < 4) ? Ahp : Alp) + go;
            cpa16(base + (isB ? 16384 : 0) + sw, src);
        }
        asm volatile("cp.async.commit_group;");
    };

    stage(0, 0);
    for (int c = 0; c < nchunk; c++) {
        if (c + 1 < nchunk) {
            stage((c + 1) & 1, (c + 1) << 5);
            asm volatile("cp.async.wait_group 1;" ::: "memory");
        } else {
            asm volatile("cp.async.wait_group 0;" ::: "memory");
        }
        __syncthreads();

        uint32_t abase = sb + (c & 1) * 24576;
        uint32_t bbase = abase + 16384;
        #pragma unroll
        for (int ks = 0; ks < 2; ks++) {
            uint32_t ah[4][4], al[4][4];
            #pragma unroll
            for (int ma = 0; ma < 4; ma++) {
                int row = wm + ma * 16 + (lane & 15);
                int ch  = ks * 2 + (lane >> 4);
                uint32_t off = row * 128 + ch * 16;
                uint32_t swh = off ^ ((off >> 3) & 0x70);
                uint32_t offl = off + 64;
                uint32_t swl = offl ^ ((offl >> 3) & 0x70);
                ldsm4(ah[ma], abase + swh);
                ldsm4(al[ma], abase + swl);
            }
            uint32_t bh[4], bl[4];
            {
                int g = lane >> 3;
                int nrow = wn + (g >> 1) * 8 + (lane & 7);
                int ch = ks * 2 + (g & 1);
                uint32_t off = nrow * 128 + ch * 16;
                uint32_t swh = off ^ ((off >> 3) & 0x70);
                uint32_t offl = off + 64;
                uint32_t swl = offl ^ ((offl >> 3) & 0x70);
                ldsm4(bh, bbase + swh);
                ldsm4(bl, bbase + swl);
            }
            #pragma unroll
            for (int ma = 0; ma < 4; ma++)
                #pragma unroll
                for (int na = 0; na < 2; na++)
                    mma16816(acc[ma][na], ah[ma], &bh[na * 2]);
            #pragma unroll
            for (int ma = 0; ma < 4; ma++)
                #pragma unroll
                for (int na = 0; na < 2; na++)
                    mma16816(acc[ma][na], ah[ma], &bl[na * 2]);
            #pragma unroll
            for (int ma = 0; ma < 4; ma++)
                #pragma unroll
                for (int na = 0; na < 2; na++)
                    mma16816(acc[ma][na], al[ma], &bh[na * 2]);
        }
        __syncthreads();
    }

    int which = colBase >> 8;
    float* op = out; const float* bp = bias;
    if (mode == 2) {
        op = (which == 0) ? out : (which == 1) ? outB : outC;
        bp = (which == 0) ? bias : (which == 1) ? biasB : biasC;
    }
    #pragma unroll
    for (int ma = 0; ma < 4; ma++) {
        #pragma unroll
        for (int half = 0; half < 2; half++) {
            long m = rowBase + wm + ma * 16 + (lane >> 2) + half * 8;
            long om = m;
            if (remap) { int b = (int)(m >> 13), t = (int)((m >> 10) & 7), hw = (int)(m & 1023);
                         om = ((long)(b * 9 + t) << 10) + hw; }
            #pragma unroll
            for (int na = 0; na < 2; na++) {
                int n0 = colBase + wn + na * 8 + (lane & 3) * 2;
                int nc = (mode == 2) ? (n0 & 255) : n0;
                float2 bv = *(const float2*)&bp[nc];
                float2 vv;
                vv.x = acc[ma][na][half * 2 + 0] + bv.x;
                vv.y = acc[ma][na][half * 2 + 1] + bv.y;
                if (mode == 1) {
                    vv.x = 0.5f * vv.x * (1.f + erff(vv.x * 0.70710678118654752f));
                    vv.y = 0.5f * vv.y * (1.f + erff(vv.y * 0.70710678118654752f));
                    __nv_bfloat16 hx, lx, hy, ly;
                    split_bf16(vv.x, hx, lx);
                    split_bf16(vv.y, hy, ly);
                    *(uint32_t*)&outh[om * M + n0] = pack2(hx, hy);
                    *(uint32_t*)&outl[om * M + n0] = pack2(lx, ly);
                } else if (mode == 2) {
                    *(float2*)&op[om * 256 + nc] = vv;
                } else {
                    if (res) {
                        float2 rv = *(const float2*)&res[om * M + n0];
                        vv.x += rv.x; vv.y += rv.y;
                    }
                    *(float2*)&op[om * M + n0] = vv;
                }
            }
        }
    }
}

// ---------------- LayerNorm -> split bf16 -----------------------------------
__global__ void ln_kernel(const float* __restrict__ in, const float* __restrict__ g,
                          const float* __restrict__ bta, __nv_bfloat16* __restrict__ outh,
                          __nv_bfloat16* __restrict__ outl, int remap)
{
    int r = blockIdx.x;
    long ir = r;
    if (remap) { int b = r >> 13, t = (r >> 10) & 7, hw = r & 1023;
                 ir = ((long)(b * 9 + t) << 10) + hw; }
    float v = in[ir * DIMN + threadIdx.x];
    __shared__ float sbuf[40];
    float s = v, q = v * v;
    #pragma unroll
    for (int o = 16; o; o >>= 1) { s += __shfl_xor_sync(~0u, s, o); q += __shfl_xor_sync(~0u, q, o); }
    int w = threadIdx.x >> 5;
    if ((threadIdx.x & 31) == 0) { sbuf[w] = s; sbuf[8 + w] = q; }
    __syncthreads();
    if (threadIdx.x < 32) {
        s = (threadIdx.x < 8) ? sbuf[threadIdx.x] : 0.f;
        q = (threadIdx.x < 8) ? sbuf[8 + threadIdx.x] : 0.f;
        #pragma unroll
        for (int o = 4; o; o >>= 1) { s += __shfl_xor_sync(~0u, s, o); q += __shfl_xor_sync(~0u, q, o); }
        if (threadIdx.x == 0) { sbuf[32] = s; sbuf[33] = q; }
    }
    __syncthreads();
    float mean = sbuf[32] * (1.f / 256.f);
    float var  = sbuf[33] * (1.f / 256.f) - mean * mean;
    float vo = (v - mean) * rsqrtf(var + 1e-5f) * g[threadIdx.x] + bta[threadIdx.x];
    __nv_bfloat16 h, l; split_bf16(vo, h, l);
    outh[(long)r * DIMN + threadIdx.x] = h;
    outl[(long)r * DIMN + threadIdx.x] = l;
}

// ---------------- Spatial windowed attention: warp = pixel (both halves) ----
__global__ void __launch_bounds__(256)
sattn_kernel(const float* __restrict__ Q, const float* __restrict__ K,
             const float* __restrict__ V,
             __nv_bfloat16* __restrict__ Oh, __nv_bfloat16* __restrict__ Ol)
{
    int warp = threadIdx.x >> 5, lane = threadIdx.x & 31;
    int r = (blockIdx.x << 3) + warp;
    int bt = r >> 10, pix = r & 1023;
    int y = pix >> 5, x = pix & 31;
    long kb = (long)bt << 10;
    const float4* Qp = (const float4*)(Q + ((long)r << 8));
    float4 qa = Qp[lane];          // heads 0-3
    float4 qb = Qp[32 + lane];     // heads 4-7
    float sa[9], sb_[9];
    #pragma unroll
    for (int n = 0; n < 9; n++) {
        int dy = n / 3 - 1, dx = n % 3 - 1;
        int ny = y + dy, nx = x + dx;
        bool ok = ((unsigned)ny < 32u) && ((unsigned)nx < 32u);
        float pa = 0.f, pb = 0.f;
        if (ok) {
            const float4* Kp = (const float4*)(K + ((kb + (ny << 5) + nx) << 8));
            float4 ka = Kp[lane];
            float4 kb2 = Kp[32 + lane];
            pa = qa.x * ka.x + qa.y * ka.y + qa.z * ka.z + qa.w * ka.w;
            pb = qb.x * kb2.x + qb.y * kb2.y + qb.z * kb2.z + qb.w * kb2.w;
        }
        pa += __shfl_xor_sync(~0u, pa, 1);
        pa += __shfl_xor_sync(~0u, pa, 2);
        pa += __shfl_xor_sync(~0u, pa, 4);
        pb += __shfl_xor_sync(~0u, pb, 1);
        pb += __shfl_xor_sync(~0u, pb, 2);
        pb += __shfl_xor_sync(~0u, pb, 4);
        sa[n]  = ok ? pa * SCALE : -1e9f;
        sb_[n] = ok ? pb * SCALE : -1e9f;
    }
    float mxa = sa[0], mxb = sb_[0];
    #pragma unroll
    for (int n = 1; n < 9; n++) { mxa = fmaxf(mxa, sa[n]); mxb = fmaxf(mxb, sb_[n]); }
    float dena = 0.f, denb = 0.f;
    #pragma unroll
    for (int n = 0; n < 9; n++) {
        sa[n]  = expf(sa[n] - mxa);  dena += sa[n];
        sb_[n] = expf(sb_[n] - mxb); denb += sb_[n];
    }
    float inva = 1.f / dena, invb = 1.f / denb;
    float4 aa = make_float4(0.f, 0.f, 0.f, 0.f);
    float4 ab = make_float4(0.f, 0.f, 0.f, 0.f);
    #pragma unroll
    for (int n = 0; n < 9; n++) {
        int dy = n / 3 - 1, dx = n % 3 - 1;
        int ny = y + dy, nx = x + dx;
        if (((unsigned)ny < 32u) && ((unsigned)nx < 32u)) {
            const float4* Vp = (const float4*)(V + ((kb + (ny << 5) + nx) << 8));
            float4 va = Vp[lane];
            float4 vb = Vp[32 + lane];
            float wa = sa[n] * inva, wb = sb_[n] * invb;
            aa.x += wa * va.x; aa.y += wa * va.y; aa.z += wa * va.z; aa.w += wa * va.w;
            ab.x += wb * vb.x; ab.y += wb * vb.y; ab.z += wb * vb.z; ab.w += wb * vb.w;
        }
    }
    __nv_bfloat16 h0, l0, h1, l1;
    long ob = ((long)r << 8) + lane * 4;
    split_bf16(aa.x, h0, l0); split_bf16(aa.y, h1, l1);
    *(uint32_t*)&Oh[ob] = pack2(h0, h1);  *(uint32_t*)&Ol[ob] = pack2(l0, l1);
    split_bf16(aa.z, h0, l0); split_bf16(aa.w, h1, l1);
    *(uint32_t*)&Oh[ob + 2] = pack2(h0, h1);  *(uint32_t*)&Ol[ob + 2] = pack2(l0, l1);
    split_bf16(ab.x, h0, l0); split_bf16(ab.y, h1, l1);
    *(uint32_t*)&Oh[ob + 128] = pack2(h0, h1);  *(uint32_t*)&Ol[ob + 128] = pack2(l0, l1);
    split_bf16(ab.z, h0, l0); split_bf16(ab.w, h1, l1);
    *(uint32_t*)&Oh[ob + 130] = pack2(h0, h1);  *(uint32_t*)&Ol[ob + 130] = pack2(l0, l1);
}

// ---------------- copy CLS/last frame (t=8) query -> X ----------------------
__global__ void copy8_kernel(const float* __restrict__ q, float* __restrict__ X)
{
    long idx = (long)blockIdx.x * 256 + threadIdx.x;
    int b = (int)(idx >> 18);
    long rem = idx & 262143;
    long off = ((long)(b * 9 + 8)) * 262144 + rem;
    X[off] = q[off];
}

// ---------------- Temporal attention, relative-RoPE -------------------------
__global__ void __launch_bounds__(288)
tattn_kernel(const float* __restrict__ Q, const float* __restrict__ K,
             const float* __restrict__ V, const unsigned char* __restrict__ mask,
             __nv_bfloat16* __restrict__ Oh, __nv_bfloat16* __restrict__ Ol)
{
    __shared__ float cs_tab[9][16], sn_tab[9][16];
    int tid = threadIdx.x;
    if (tid < 144) {
        int t = tid >> 4, i = tid & 15;
        float ang = (float)t * exp2f(-(float)i * 0.83048202372184058696f);
        float s_, c_; sincosf(ang, &s_, &c_);
        cs_tab[t][i] = c_; sn_tab[t][i] = s_;
    }
    __syncthreads();
    int b = blockIdx.x >> 10, hw = blockIdx.x & 1023;
    int tq = tid >> 5, lane = tid & 31;
    long base = ((long)b * TQN) << 10;
    long qrow = base + ((long)tq << 10) + hw;

    const float4* Qp = (const float4*)(Q + (qrow << 8));
    float4 q0 = Qp[lane * 2], q1 = Qp[lane * 2 + 1];
    float4 p0, p1;
    p0.x = __shfl_xor_sync(~0u, q0.x, 2); p0.y = __shfl_xor_sync(~0u, q0.y, 2);
    p0.z = __shfl_xor_sync(~0u, q0.z, 2); p0.w = __shfl_xor_sync(~0u, q0.w, 2);
    p1.x = __shfl_xor_sync(~0u, q1.x, 2); p1.y = __shfl_xor_sync(~0u, q1.y, 2);
    p1.z = __shfl_xor_sync(~0u, q1.z, 2); p1.w = __shfl_xor_sync(~0u, q1.w, 2);
    bool fh = ((lane & 2) == 0);
    int i0 = ((lane & 3) * 8) & 15;    // 0 or 8

    float sc[9];
    #pragma unroll
    for (int tk = 0; tk < 9; tk++) {
        int rel = tq - tk;
        int ar = (rel < 0) ? -rel : rel;
        float sg = (rel < 0) ? -1.f : 1.f;
        const float* cs = cs_tab[ar];
        const float* sn = sn_tab[ar];
        float qr[8];
        #pragma unroll
        for (int j = 0; j < 8; j++) {
            float qc = (j < 4) ? ((const float*)&q0)[j] : ((const float*)&q1)[j - 4];
            float pc = (j < 4) ? ((const float*)&p0)[j] : ((const float*)&p1)[j - 4];
            float c_ = cs[i0 + j], s_ = sg * sn[i0 + j];
            qr[j] = fh ? (qc * c_ - pc * s_) : (pc * s_ + qc * c_);
        }
        long krow = base + ((long)tk << 10) + hw;
        const float4* Kp = (const float4*)(K + (krow << 8));
        float4 k0 = Kp[lane * 2], k1 = Kp[lane * 2 + 1];
        float p = qr[0] * k0.x + qr[1] * k0.y + qr[2] * k0.z + qr[3] * k0.w
                + qr[4] * k1.x + qr[5] * k1.y + qr[6] * k1.z + qr[7] * k1.w;
        p += __shfl_xor_sync(~0u, p, 1);
        p += __shfl_xor_sync(~0u, p, 2);
        sc[tk] = mask[tq * 9 + tk] ? -1e9f : p * SCALE;
    }
    float mx = sc[0];
    #pragma unroll
    for (int t = 1; t < 9; t++) mx = fmaxf(mx, sc[t]);
    float den = 0.f;
    #pragma unroll
    for (int t = 0; t < 9; t++) { sc[t] = expf(sc[t] - mx); den += sc[t]; }
    float inv = 1.f / den;
    float a[8];
    #pragma unroll
    for (int j = 0; j < 8; j++) a[j] = 0.f;
    #pragma unroll
    for (int tk = 0; tk < 9; tk++) {
        long krow = base + ((long)tk << 10) + hw;
        const float4* Vp = (const float4*)(V + (krow << 8));
        float4 v0 = Vp[lane * 2], v1 = Vp[lane * 2 + 1];
        float w = sc[tk] * inv;
        a[0] += w * v0.x; a[1] += w * v0.y; a[2] += w * v0.z; a[3] += w * v0.w;
        a[4] += w * v1.x; a[5] += w * v1.y; a[6] += w * v1.z; a[7] += w * v1.w;
    }
    uint4 hv, lv;
    {
        __nv_bfloat16 h0,l0,h1,l1;
        split_bf16(a[0],h0,l0); split_bf16(a[1],h1,l1); hv.x = pack2(h0,h1); lv.x = pack2(l0,l1);
        split_bf16(a[2],h0,l0); split_bf16(a[3],h1,l1); hv.y = pack2(h0,h1); lv.y = pack2(l0,l1);
        split_bf16(a[4],h0,l0); split_bf16(a[5],h1,l1); hv.z = pack2(h0,h1); lv.z = pack2(l0,l1);
        split_bf16(a[6],h0,l0); split_bf16(a[7],h1,l1); hv.w = pack2(h0,h1); lv.w = pack2(l0,l1);
    }
    long ob = (qrow << 8) + lane * 8;
    *(uint4*)&Oh[ob] = hv;
    *(uint4*)&Ol[ob] = lv;
}

// ---------------- CLS frame (t=0): parallel reduce + broadcast --------------
__global__ void cls_reduce_kernel(const float* __restrict__ X, float* __restrict__ P)
{
    int chunk = blockIdx.x, b = blockIdx.y, d = threadIdx.x;
    long base = (long)(b * 9) * HWN * DIMN + (long)chunk * 128 * DIMN;
    float s = 0.f;
    #pragma unroll 4
    for (int hw = 0; hw < 128; hw++) s += X[base + (long)hw * DIMN + d];
    P[((long)b * 8 + chunk) * DIMN + d] = s;
}
__global__ void cls_bcast_kernel(const float* __restrict__ P, float* __restrict__ X)
{
    int chunk = blockIdx.x, b = blockIdx.y, d = threadIdx.x;
    float s = 0.f;
    #pragma unroll
    for (int c = 0; c < 8; c++) s += P[((long)b * 8 + c) * DIMN + d];
    s *= (1.f / 1024.f);
    long base = (long)(b * 9) * HWN * DIMN + (long)chunk * 128 * DIMN;
    #pragma unroll 4
    for (int hw = 0; hw < 128; hw++) X[base + (long)hw * DIMN + d] = s;
}

// ---------------- launch ----------------------------------------------------
#define O_SQKV 0
#define O_SWO 196608
#define O_TQKV 262144
#define O_TWO 458752
#define O_W1  524288
#define O_W2  786432

extern "C" void kernel_launch(void* const* d_in, const int* in_sizes, int n_in,
                              void* d_out, int out_size)
{
    const float* query = (const float*)d_in[0];
    const unsigned char* tmask = (const unsigned char*)d_in[2];
    const float* sln_g = (const float*)d_in[3];
    const float* sln_b = (const float*)d_in[4];
    const float* s_wq = (const float*)d_in[5];  const float* s_bq = (const float*)d_in[6];
    const float* s_wk = (const float*)d_in[7];  const float* s_bk = (const float*)d_in[8];
    const float* s_wv = (const float*)d_in[9];  const float* s_bv = (const float*)d_in[10];
    const float* s_wo = (const float*)d_in[11]; const float* s_bo = (const float*)d_in[12];
    const float* tln_g = (const float*)d_in[13];
    const float* tln_b = (const float*)d_in[14];
    const float* t_wq = (const float*)d_in[15]; const float* t_bq = (const float*)d_in[16];
    const float* t_wk = (const float*)d_in[17]; const float* t_bk = (const float*)d_in[18];
    const float* t_wv = (const float*)d_in[19]; const float* t_bv = (const float*)d_in[20];
    const float* t_wo = (const float*)d_in[21]; const float* t_bo = (const float*)d_in[22];
    const float* mln_g = (const float*)d_in[23];
    const float* mln_b = (const float*)d_in[24];
    const float* w1 = (const float*)d_in[25];   const float* b1 = (const float*)d_in[26];
    const float* w2 = (const float*)d_in[27];   const float* b2 = (const float*)d_in[28];
    float* out = (float*)d_out;

    float *q, *k, *v, *x, *clsp;
    __nv_bfloat16 *xnh, *xnl, *oh, *ol, *hh, *hl, *wth, *wtl;
    cudaGetSymbolAddress((void**)&q,  g_q);
    cudaGetSymbolAddress((void**)&k,  g_k);
    cudaGetSymbolAddress((void**)&v,  g_v);
    cudaGetSymbolAddress((void**)&x,  g_x);
    cudaGetSymbolAddress((void**)&clsp, g_clsp);
    cudaGetSymbolAddress((void**)&xnh, g_xnh);
    cudaGetSymbolAddress((void**)&xnl, g_xnl);
    cudaGetSymbolAddress((void**)&oh,  g_oh);
    cudaGetSymbolAddress((void**)&ol,  g_ol);
    cudaGetSymbolAddress((void**)&hh,  g_hh);
    cudaGetSymbolAddress((void**)&hl,  g_hl);
    cudaGetSymbolAddress((void**)&wth, g_wth);
    cudaGetSymbolAddress((void**)&wtl, g_wtl);

    cudaFuncSetAttribute(mmagemm, cudaFuncAttributeMaxDynamicSharedMemorySize, MMA_SMEM);

    wsplit_all<<<1024, dim3(32, 8)>>>(s_wq, s_wk, s_wv, s_wo, t_wq, t_wk, t_wv, t_wo,
                                      w1, w2, wth, wtl);

    // ---- spatial block ----
    ln_kernel<<<NROWS_SP, 256>>>(query, sln_g, sln_b, xnh, xnl, 1);
    mmagemm<<<dim3(12, NROWS_SP/128), 256, MMA_SMEM>>>(xnh, xnl, wth+O_SQKV, wtl+O_SQKV,
        s_bq, s_bk, s_bv, nullptr, q, k, v, nullptr, nullptr, 256, 256, 2, 0);
    sattn_kernel<<<NROWS_SP/8, 256>>>(q, k, v, oh, ol);
    mmagemm<<<dim3(4, NROWS_SP/128), 256, MMA_SMEM>>>(oh, ol, wth+O_SWO, wtl+O_SWO,
        s_bo, nullptr, nullptr, query, x, nullptr, nullptr, nullptr, nullptr, 256, 256, 0, 1);
    copy8_kernel<<<4096, 256>>>(query, x);

    // ---- temporal block ----
    ln_kernel<<<NROWS, 256>>>(x, tln_g, tln_b, xnh, xnl, 0);
    mmagemm<<<dim3(12, NROWS/128), 256, MMA_SMEM>>>(xnh, xnl, wth+O_TQKV, wtl+O_TQKV,
        t_bq, t_bk, t_bv, nullptr, q, k, v, nullptr, nullptr, 256, 256, 2, 0);
    tattn_kernel<<<BATCH*HWN, 288>>>(q, k, v, tmask, oh, ol);
    mmagemm<<<dim3(4, NROWS/128), 256, MMA_SMEM>>>(oh, ol, wth+O_TWO, wtl+O_TWO,
        t_bo, nullptr, nullptr, x, x, nullptr, nullptr, nullptr, nullptr, 256, 256, 0, 0);

    // ---- CLS average ----
    cls_reduce_kernel<<<dim3(8, 4), 256>>>(x, clsp);
    cls_bcast_kernel<<<dim3(8, 4), 256>>>(clsp, x);

    // ---- MLP ----
    ln_kernel<<<NROWS, 256>>>(x, mln_g, mln_b, xnh, xnl, 0);
    mmagemm<<<dim3(16, NROWS/128), 256, MMA_SMEM>>>(xnh, xnl, wth+O_W1, wtl+O_W1,
        b1, nullptr, nullptr, nullptr, nullptr, nullptr, nullptr, hh, hl, 1024, 256, 1, 0);
    mmagemm<<<dim3(4, NROWS/128), 256, MMA_SMEM>>>(hh, hl, wth+O_W2, wtl+O_W2,
        b2, nullptr, nullptr, x, out, nullptr, nullptr, nullptr, nullptr, 256, 1024, 0, 0);
}

// round 17
// speedup vs baseline: 1.7654x; 1.7654x over previous
#include <cuda_runtime.h>
#include <cuda_fp16.h>
#include <math.h>
#include <stdint.h>

// Problem constants
#define BATCH 4
#define TQN   9
#define TFR   8
#define HWN   1024
#define DIMN  256
#define NHN   8
#define DHN   32
#define MLPD  1024
#define NROWS    (BATCH*TQN*HWN)   // 36864
#define NROWS_SP (BATCH*TFR*HWN)   // 32768
#define SCALE 0.17677669529663687f

// ---------------- scratch ----------------------------------------------
__device__ __align__(16) float g_q [NROWS*DIMN];
__device__ __align__(16) float g_k [NROWS*DIMN];
__device__ __align__(16) float g_v [NROWS*DIMN];
__device__ __align__(16) float g_x [NROWS*DIMN];
__device__ __align__(16) float g_clsp[BATCH*8*DIMN];
__device__ __align__(16) __half g_xn[NROWS*DIMN];
__device__ __align__(16) __half g_o [NROWS*DIMN];
__device__ __align__(16) __half g_h [(long)NROWS*MLPD];
__device__ __align__(16) __half g_wt[1048576];

// ---------------- helpers ----------------------------------------------
__device__ __forceinline__ uint32_t s2u(const void* p) {
    uint32_t a;
    asm("{ .reg .u64 t; cvta.to.shared.u64 t, %1; cvt.u32.u64 %0, t; }" : "=r"(a) : "l"(p));
    return a;
}
__device__ __forceinline__ void ldsm4(uint32_t* r, uint32_t addr) {
    asm volatile("ldmatrix.sync.aligned.m8n8.x4.shared.b16 {%0,%1,%2,%3}, [%4];"
                 : "=r"(r[0]), "=r"(r[1]), "=r"(r[2]), "=r"(r[3]) : "r"(addr));
}
__device__ __forceinline__ void mma16816(float* d, const uint32_t* a, const uint32_t* b) {
    asm volatile("mma.sync.aligned.m16n8k16.row.col.f32.f16.f16.f32 "
                 "{%0,%1,%2,%3}, {%4,%5,%6,%7}, {%8,%9}, {%0,%1,%2,%3};"
                 : "+f"(d[0]), "+f"(d[1]), "+f"(d[2]), "+f"(d[3])
                 : "r"(a[0]), "r"(a[1]), "r"(a[2]), "r"(a[3]), "r"(b[0]), "r"(b[1]));
}
__device__ __forceinline__ void cpa16(uint32_t sm, const void* g) {
    asm volatile("cp.async.cg.shared.global [%0], [%1], 16;" :: "r"(sm), "l"(g));
}
__device__ __forceinline__ uint32_t pack2h(__half a, __half b) {
    return ((uint32_t)__half_as_ushort(b) << 16) | __half_as_ushort(a);
}

// ---------------- all-weights transpose -> fp16 ------------------------------
__global__ void wsplit_all(const float* s0, const float* s1, const float* s2, const float* s3,
                           const float* s4, const float* s5, const float* s6, const float* s7,
                           const float* s8, const float* s9, __half* __restrict__ Th)
{
    __shared__ float tile[32][33];
    int t = blockIdx.x;
    const float* W; long dst; int K, M, mtile, ktile;
    if (t < 512) {
        int j = t >> 6, wi = t & 63;
        K = 256; M = 256; mtile = wi & 7; ktile = wi >> 3;
        dst = (long)j * 65536;
        switch (j) {
            case 0: W = s0; break; case 1: W = s1; break; case 2: W = s2; break;
            case 3: W = s3; break; case 4: W = s4; break; case 5: W = s5; break;
            case 6: W = s6; break; default: W = s7; break;
        }
    } else if (t < 768) {
        int wi = t - 512;
        K = 256; M = 1024; mtile = wi & 31; ktile = wi >> 5;
        dst = 524288; W = s8;
    } else {
        int wi = t - 768;
        K = 1024; M = 256; mtile = wi & 7; ktile = wi >> 3;
        dst = 786432; W = s9;
    }
    int mb = mtile * 32, kb = ktile * 32;
    int tx = threadIdx.x, ty = threadIdx.y;
    #pragma unroll
    for (int i = 0; i < 32; i += 8)
        tile[ty + i][tx] = W[(long)(kb + ty + i) * M + mb + tx];
    __syncthreads();
    #pragma unroll
    for (int i = 0; i < 32; i += 8) {
        long o = dst + (long)(mb + ty + i) * K + kb + tx;
        Th[o] = __float2half_rn(tile[tx][ty + i]);
    }
}

// ---------------- mma.sync fp16 single-pass GEMM -----------------------------
// 128x128 tile, BK=64 (round-7-verified addressing), 2-stage cp.async.
// Stage: A 16KB @ +0, B 16KB @ +16384; stage stride 32768.
#define MMA_SMEM 65536

__global__ void __launch_bounds__(256, 2)
mmagemm(const __half* __restrict__ Ah, const __half* __restrict__ Wh,
        const float* __restrict__ bias, const float* __restrict__ biasB,
        const float* __restrict__ biasC, const float* __restrict__ res,
        float* __restrict__ out, float* __restrict__ outB, float* __restrict__ outC,
        __half* __restrict__ outh, int M, int K, int mode, int remap)
{
    extern __shared__ __align__(1024) char smem[];
    uint32_t sb = s2u(smem);
    int tid = threadIdx.x, wid = tid >> 5, lane = tid & 31;
    int wm = (wid & 1) * 64, wn = (wid >> 1) * 32;

    long rowBase = (long)blockIdx.y * 128;
    int  colBase = blockIdx.x * 128;
    const __half* Ahp = Ah + rowBase * K;
    const __half* Whp = Wh + (long)colBase * K;

    float acc[4][4][4];
    #pragma unroll
    for (int i = 0; i < 4; i++)
        #pragma unroll
        for (int j = 0; j < 4; j++)
            #pragma unroll
            for (int tt = 0; tt < 4; tt++) acc[i][j][tt] = 0.f;

    int nchunk = K >> 6;

    // 2048 16B slots: 0..1023 = A rows, 1024..2047 = B rows (128B = 64 fp16/row)
    auto stage = [&](int s, int kbase) {
        uint32_t base = sb + s * 32768;
        #pragma unroll
        for (int i = 0; i < 8; i++) {
            int slot = tid + i * 256;
            int half_ = slot >> 10;
            int s2 = slot & 1023;
            int row = s2 >> 3;
            int cch = s2 & 7;
            uint32_t off = row * 128 + cch * 16;
            uint32_t sw = off ^ ((off >> 3) & 0x70);
            long go = (long)row * K + kbase + cch * 8;
            const __half* src = half_ ? (Whp + go) : (Ahp + go);
            cpa16(base + half_ * 16384 + sw, src);
        }
        asm volatile("cp.async.commit_group;");
    };

    stage(0, 0);
    for (int c = 0; c < nchunk; c++) {
        if (c + 1 < nchunk) {
            stage((c + 1) & 1, (c + 1) << 6);
            asm volatile("cp.async.wait_group 1;" ::: "memory");
        } else {
            asm volatile("cp.async.wait_group 0;" ::: "memory");
        }
        __syncthreads();

        uint32_t abase = sb + (c & 1) * 32768;
        uint32_t bbase = abase + 16384;
        #pragma unroll
        for (int ks = 0; ks < 4; ks++) {
            uint32_t ah[4][4];
            #pragma unroll
            for (int ma = 0; ma < 4; ma++) {
                int row = wm + ma * 16 + (lane & 15);
                int ch  = ks * 2 + (lane >> 4);
                uint32_t off = row * 128 + ch * 16;
                uint32_t sw = off ^ ((off >> 3) & 0x70);
                ldsm4(ah[ma], abase + sw);
            }
            uint32_t bh[2][4];
            #pragma unroll
            for (int np = 0; np < 2; np++) {
                int g = lane >> 3;
                int nrow = wn + np * 16 + (g >> 1) * 8 + (lane & 7);
                int ch = ks * 2 + (g & 1);
                uint32_t off = nrow * 128 + ch * 16;
                uint32_t sw = off ^ ((off >> 3) & 0x70);
                ldsm4(bh[np], bbase + sw);
            }
            #pragma unroll
            for (int ma = 0; ma < 4; ma++)
                #pragma unroll
                for (int na = 0; na < 4; na++)
                    mma16816(acc[ma][na], ah[ma], &bh[na >> 1][(na & 1) * 2]);
        }
        __syncthreads();
    }

    int which = colBase >> 8;
    float* op = out; const float* bp = bias;
    if (mode == 2) {
        op = (which == 0) ? out : (which == 1) ? outB : outC;
        bp = (which == 0) ? bias : (which == 1) ? biasB : biasC;
    }
    #pragma unroll
    for (int ma = 0; ma < 4; ma++) {
        #pragma unroll
        for (int half_ = 0; half_ < 2; half_++) {
            long m = rowBase + wm + ma * 16 + (lane >> 2) + half_ * 8;
            long om = m;
            if (remap) { int b = (int)(m >> 13), t = (int)((m >> 10) & 7), hw = (int)(m & 1023);
                         om = ((long)(b * 9 + t) << 10) + hw; }
            #pragma unroll
            for (int na = 0; na < 4; na++) {
                int n0 = colBase + wn + na * 8 + (lane & 3) * 2;
                int nc = (mode == 2) ? (n0 & 255) : n0;
                float2 bv = *(const float2*)&bp[nc];
                float2 vv;
                vv.x = acc[ma][na][half_ * 2 + 0] + bv.x;
                vv.y = acc[ma][na][half_ * 2 + 1] + bv.y;
                if (mode == 1) {
                    vv.x = 0.5f * vv.x * (1.f + erff(vv.x * 0.70710678118654752f));
                    vv.y = 0.5f * vv.y * (1.f + erff(vv.y * 0.70710678118654752f));
                    *(uint32_t*)&outh[om * M + n0] =
                        pack2h(__float2half_rn(vv.x), __float2half_rn(vv.y));
                } else if (mode == 2) {
                    *(float2*)&op[om * 256 + nc] = vv;
                } else {
                    if (res) {
                        float2 rv = *(const float2*)&res[om * M + n0];
                        vv.x += rv.x; vv.y += rv.y;
                    }
                    *(float2*)&op[om * M + n0] = vv;
                }
            }
        }
    }
}

// ---------------- LayerNorm -> fp16 ------------------------------------------
__global__ void ln_kernel(const float* __restrict__ in, const float* __restrict__ g,
                          const float* __restrict__ bta, __half* __restrict__ outh, int remap)
{
    int r = blockIdx.x;
    long ir = r;
    if (remap) { int b = r >> 13, t = (r >> 10) & 7, hw = r & 1023;
                 ir = ((long)(b * 9 + t) << 10) + hw; }
    float v = in[ir * DIMN + threadIdx.x];
    __shared__ float sbuf[40];
    float s = v, q = v * v;
    #pragma unroll
    for (int o = 16; o; o >>= 1) { s += __shfl_xor_sync(~0u, s, o); q += __shfl_xor_sync(~0u, q, o); }
    int w = threadIdx.x >> 5;
    if ((threadIdx.x & 31) == 0) { sbuf[w] = s; sbuf[8 + w] = q; }
    __syncthreads();
    if (threadIdx.x < 32) {
        s = (threadIdx.x < 8) ? sbuf[threadIdx.x] : 0.f;
        q = (threadIdx.x < 8) ? sbuf[8 + threadIdx.x] : 0.f;
        #pragma unroll
        for (int o = 4; o; o >>= 1) { s += __shfl_xor_sync(~0u, s, o); q += __shfl_xor_sync(~0u, q, o); }
        if (threadIdx.x == 0) { sbuf[32] = s; sbuf[33] = q; }
    }
    __syncthreads();
    float mean = sbuf[32] * (1.f / 256.f);
    float var  = sbuf[33] * (1.f / 256.f) - mean * mean;
    float vo = (v - mean) * rsqrtf(var + 1e-5f) * g[threadIdx.x] + bta[threadIdx.x];
    outh[(long)r * DIMN + threadIdx.x] = __float2half_rn(vo);
}

// ---------------- Spatial windowed attention: warp = pixel (both halves) ----
__global__ void __launch_bounds__(256)
sattn_kernel(const float* __restrict__ Q, const float* __restrict__ K,
             const float* __restrict__ V, __half* __restrict__ Oh)
{
    int warp = threadIdx.x >> 5, lane = threadIdx.x & 31;
    int r = (blockIdx.x << 3) + warp;
    int bt = r >> 10, pix = r & 1023;
    int y = pix >> 5, x = pix & 31;
    long kb = (long)bt << 10;
    const float4* Qp = (const float4*)(Q + ((long)r << 8));
    float4 qa = Qp[lane];          // heads 0-3
    float4 qb = Qp[32 + lane];     // heads 4-7
    float sa[9], sb_[9];
    #pragma unroll
    for (int n = 0; n < 9; n++) {
        int dy = n / 3 - 1, dx = n % 3 - 1;
        int ny = y + dy, nx = x + dx;
        bool ok = ((unsigned)ny < 32u) && ((unsigned)nx < 32u);
        float pa = 0.f, pb = 0.f;
        if (ok) {
            const float4* Kp = (const float4*)(K + ((kb + (ny << 5) + nx) << 8));
            float4 ka = Kp[lane];
            float4 kb2 = Kp[32 + lane];
            pa = qa.x * ka.x + qa.y * ka.y + qa.z * ka.z + qa.w * ka.w;
            pb = qb.x * kb2.x + qb.y * kb2.y + qb.z * kb2.z + qb.w * kb2.w;
        }
        pa += __shfl_xor_sync(~0u, pa, 1);
        pa += __shfl_xor_sync(~0u, pa, 2);
        pa += __shfl_xor_sync(~0u, pa, 4);
        pb += __shfl_xor_sync(~0u, pb, 1);
        pb += __shfl_xor_sync(~0u, pb, 2);
        pb += __shfl_xor_sync(~0u, pb, 4);
        sa[n]  = ok ? pa * SCALE : -1e9f;
        sb_[n] = ok ? pb * SCALE : -1e9f;
    }
    float mxa = sa[0], mxb = sb_[0];
    #pragma unroll
    for (int n = 1; n < 9; n++) { mxa = fmaxf(mxa, sa[n]); mxb = fmaxf(mxb, sb_[n]); }
    float dena = 0.f, denb = 0.f;
    #pragma unroll
    for (int n = 0; n < 9; n++) {
        sa[n]  = expf(sa[n] - mxa);  dena += sa[n];
        sb_[n] = expf(sb_[n] - mxb); denb += sb_[n];
    }
    float inva = 1.f / dena, invb = 1.f / denb;
    float4 aa = make_float4(0.f, 0.f, 0.f, 0.f);
    float4 ab = make_float4(0.f, 0.f, 0.f, 0.f);
    #pragma unroll
    for (int n = 0; n < 9; n++) {
        int dy = n / 3 - 1, dx = n % 3 - 1;
        int ny = y + dy, nx = x + dx;
        if (((unsigned)ny < 32u) && ((unsigned)nx < 32u)) {
            const float4* Vp = (const float4*)(V + ((kb + (ny << 5) + nx) << 8));
            float4 va = Vp[lane];
            float4 vb = Vp[32 + lane];
            float wa = sa[n] * inva, wb = sb_[n] * invb;
            aa.x += wa * va.x; aa.y += wa * va.y; aa.z += wa * va.z; aa.w += wa * va.w;
            ab.x += wb * vb.x; ab.y += wb * vb.y; ab.z += wb * vb.z; ab.w += wb * vb.w;
        }
    }
    long ob = ((long)r << 8) + lane * 4;
    *(uint32_t*)&Oh[ob]       = pack2h(__float2half_rn(aa.x), __float2half_rn(aa.y));
    *(uint32_t*)&Oh[ob + 2]   = pack2h(__float2half_rn(aa.z), __float2half_rn(aa.w));
    *(uint32_t*)&Oh[ob + 128] = pack2h(__float2half_rn(ab.x), __float2half_rn(ab.y));
    *(uint32_t*)&Oh[ob + 130] = pack2h(__float2half_rn(ab.z), __float2half_rn(ab.w));
}

// ---------------- copy CLS/last frame (t=8) query -> X ----------------------
__global__ void copy8_kernel(const float* __restrict__ q, float* __restrict__ X)
{
    long idx = (long)blockIdx.x * 256 + threadIdx.x;
    int b = (int)(idx >> 18);
    long rem = idx & 262143;
    long off = ((long)(b * 9 + 8)) * 262144 + rem;
    X[off] = q[off];
}

// ---------------- Temporal attention, relative-RoPE -------------------------
__global__ void __launch_bounds__(288)
tattn_kernel(const float* __restrict__ Q, const float* __restrict__ K,
             const float* __restrict__ V, const unsigned char* __restrict__ mask,
             __half* __restrict__ Oh)
{
    __shared__ float cs_tab[9][16], sn_tab[9][16];
    int tid = threadIdx.x;
    if (tid < 144) {
        int t = tid >> 4, i = tid & 15;
        float ang = (float)t * exp2f(-(float)i * 0.83048202372184058696f);
        float s_, c_; sincosf(ang, &s_, &c_);
        cs_tab[t][i] = c_; sn_tab[t][i] = s_;
    }
    __syncthreads();
    int b = blockIdx.x >> 10, hw = blockIdx.x & 1023;
    int tq = tid >> 5, lane = tid & 31;
    long base = ((long)b * TQN) << 10;
    long qrow = base + ((long)tq << 10) + hw;

    const float4* Qp = (const float4*)(Q + (qrow << 8));
    float4 q0 = Qp[lane * 2], q1 = Qp[lane * 2 + 1];
    float4 p0, p1;
    p0.x = __shfl_xor_sync(~0u, q0.x, 2); p0.y = __shfl_xor_sync(~0u, q0.y, 2);
    p0.z = __shfl_xor_sync(~0u, q0.z, 2); p0.w = __shfl_xor_sync(~0u, q0.w, 2);
    p1.x = __shfl_xor_sync(~0u, q1.x, 2); p1.y = __shfl_xor_sync(~0u, q1.y, 2);
    p1.z = __shfl_xor_sync(~0u, q1.z, 2); p1.w = __shfl_xor_sync(~0u, q1.w, 2);
    bool fh = ((lane & 2) == 0);
    int i0 = ((lane & 3) * 8) & 15;    // 0 or 8

    float sc[9];
    #pragma unroll
    for (int tk = 0; tk < 9; tk++) {
        int rel = tq - tk;
        int ar = (rel < 0) ? -rel : rel;
        float sg = (rel < 0) ? -1.f : 1.f;
        const float* cs = cs_tab[ar];
        const float* sn = sn_tab[ar];
        float qr[8];
        #pragma unroll
        for (int j = 0; j < 8; j++) {
            float qc = (j < 4) ? ((const float*)&q0)[j] : ((const float*)&q1)[j - 4];
            float pc = (j < 4) ? ((const float*)&p0)[j] : ((const float*)&p1)[j - 4];
            float c_ = cs[i0 + j], s_ = sg * sn[i0 + j];
            qr[j] = fh ? (qc * c_ - pc * s_) : (pc * s_ + qc * c_);
        }
        long krow = base + ((long)tk << 10) + hw;
        const float4* Kp = (const float4*)(K + (krow << 8));
        float4 k0 = Kp[lane * 2], k1 = Kp[lane * 2 + 1];
        float p = qr[0] * k0.x + qr[1] * k0.y + qr[2] * k0.z + qr[3] * k0.w
                + qr[4] * k1.x + qr[5] * k1.y + qr[6] * k1.z + qr[7] * k1.w;
        p += __shfl_xor_sync(~0u, p, 1);
        p += __shfl_xor_sync(~0u, p, 2);
        sc[tk] = mask[tq * 9 + tk] ? -1e9f : p * SCALE;
    }
    float mx = sc[0];
    #pragma unroll
    for (int t = 1; t < 9; t++) mx = fmaxf(mx, sc[t]);
    float den = 0.f;
    #pragma unroll
    for (int t = 0; t < 9; t++) { sc[t] = expf(sc[t] - mx); den += sc[t]; }
    float inv = 1.f / den;
    float a[8];
    #pragma unroll
    for (int j = 0; j < 8; j++) a[j] = 0.f;
    #pragma unroll
    for (int tk = 0; tk < 9; tk++) {
        long krow = base + ((long)tk << 10) + hw;
        const float4* Vp = (const float4*)(V + (krow << 8));
        float4 v0 = Vp[lane * 2], v1 = Vp[lane * 2 + 1];
        float w = sc[tk] * inv;
        a[0] += w * v0.x; a[1] += w * v0.y; a[2] += w * v0.z; a[3] += w * v0.w;
        a[4] += w * v1.x; a[5] += w * v1.y; a[6] += w * v1.z; a[7] += w * v1.w;
    }
    uint4 hv;
    hv.x = pack2h(__float2half_rn(a[0]), __float2half_rn(a[1]));
    hv.y = pack2h(__float2half_rn(a[2]), __float2half_rn(a[3]));
    hv.z = pack2h(__float2half_rn(a[4]), __float2half_rn(a[5]));
    hv.w = pack2h(__float2half_rn(a[6]), __float2half_rn(a[7]));
    long ob = (qrow << 8) + lane * 8;
    *(uint4*)&Oh[ob] = hv;
}

// ---------------- CLS frame (t=0): parallel reduce + broadcast --------------
__global__ void cls_reduce_kernel(const float* __restrict__ X, float* __restrict__ P)
{
    int chunk = blockIdx.x, b = blockIdx.y, d = threadIdx.x;
    long base = (long)(b * 9) * HWN * DIMN + (long)chunk * 128 * DIMN;
    float s = 0.f;
    #pragma unroll 4
    for (int hw = 0; hw < 128; hw++) s += X[base + (long)hw * DIMN + d];
    P[((long)b * 8 + chunk) * DIMN + d] = s;
}
__global__ void cls_bcast_kernel(const float* __restrict__ P, float* __restrict__ X)
{
    int chunk = blockIdx.x, b = blockIdx.y, d = threadIdx.x;
    float s = 0.f;
    #pragma unroll
    for (int c = 0; c < 8; c++) s += P[((long)b * 8 + c) * DIMN + d];
    s *= (1.f / 1024.f);
    long base = (long)(b * 9) * HWN * DIMN + (long)chunk * 128 * DIMN;
    #pragma unroll 4
    for (int hw = 0; hw < 128; hw++) X[base + (long)hw * DIMN + d] = s;
}

// ---------------- launch ----------------------------------------------------
#define O_SQKV 0
#define O_SWO 196608
#define O_TQKV 262144
#define O_TWO 458752
#define O_W1  524288
#define O_W2  786432

extern "C" void kernel_launch(void* const* d_in, const int* in_sizes, int n_in,
                              void* d_out, int out_size)
{
    const float* query = (const float*)d_in[0];
    const unsigned char* tmask = (const unsigned char*)d_in[2];
    const float* sln_g = (const float*)d_in[3];
    const float* sln_b = (const float*)d_in[4];
    const float* s_wq = (const float*)d_in[5];  const float* s_bq = (const float*)d_in[6];
    const float* s_wk = (const float*)d_in[7];  const float* s_bk = (const float*)d_in[8];
    const float* s_wv = (const float*)d_in[9];  const float* s_bv = (const float*)d_in[10];
    const float* s_wo = (const float*)d_in[11]; const float* s_bo = (const float*)d_in[12];
    const float* tln_g = (const float*)d_in[13];
    const float* tln_b = (const float*)d_in[14];
    const float* t_wq = (const float*)d_in[15]; const float* t_bq = (const float*)d_in[16];
    const float* t_wk = (const float*)d_in[17]; const float* t_bk = (const float*)d_in[18];
    const float* t_wv = (const float*)d_in[19]; const float* t_bv = (const float*)d_in[20];
    const float* t_wo = (const float*)d_in[21]; const float* t_bo = (const float*)d_in[22];
    const float* mln_g = (const float*)d_in[23];
    const float* mln_b = (const float*)d_in[24];
    const float* w1 = (const float*)d_in[25];   const float* b1 = (const float*)d_in[26];
    const float* w2 = (const float*)d_in[27];   const float* b2 = (const float*)d_in[28];
    float* out = (float*)d_out;

    float *q, *k, *v, *x, *clsp;
    __half *xn, *o, *h, *wt;
    cudaGetSymbolAddress((void**)&q,  g_q);
    cudaGetSymbolAddress((void**)&k,  g_k);
    cudaGetSymbolAddress((void**)&v,  g_v);
    cudaGetSymbolAddress((void**)&x,  g_x);
    cudaGetSymbolAddress((void**)&clsp, g_clsp);
    cudaGetSymbolAddress((void**)&xn, g_xn);
    cudaGetSymbolAddress((void**)&o,  g_o);
    cudaGetSymbolAddress((void**)&h,  g_h);
    cudaGetSymbolAddress((void**)&wt, g_wt);

    cudaFuncSetAttribute(mmagemm, cudaFuncAttributeMaxDynamicSharedMemorySize, MMA_SMEM);

    wsplit_all<<<1024, dim3(32, 8)>>>(s_wq, s_wk, s_wv, s_wo, t_wq, t_wk, t_wv, t_wo,
                                      w1, w2, wt);

    // ---- spatial block ----
    ln_kernel<<<NROWS_SP, 256>>>(query, sln_g, sln_b, xn, 1);
    mmagemm<<<dim3(6, NROWS_SP/128), 256, MMA_SMEM>>>(xn, wt+O_SQKV,
        s_bq, s_bk, s_bv, nullptr, q, k, v, nullptr, 256, 256, 2, 0);
    sattn_kernel<<<NROWS_SP/8, 256>>>(q, k, v, o);
    mmagemm<<<dim3(2, NROWS_SP/128), 256, MMA_SMEM>>>(o, wt+O_SWO,
        s_bo, nullptr, nullptr, query, x, nullptr, nullptr, nullptr, 256, 256, 0, 1);
    copy8_kernel<<<4096, 256>>>(query, x);

    // ---- temporal block ----
    ln_kernel<<<NROWS, 256>>>(x, tln_g, tln_b, xn, 0);
    mmagemm<<<dim3(6, NROWS/128), 256, MMA_SMEM>>>(xn, wt+O_TQKV,
        t_bq, t_bk, t_bv, nullptr, q, k, v, nullptr, 256, 256, 2, 0);
    tattn_kernel<<<BATCH*HWN, 288>>>(q, k, v, tmask, o);
    mmagemm<<<dim3(2, NROWS/128), 256, MMA_SMEM>>>(o, wt+O_TWO,
        t_bo, nullptr, nullptr, x, x, nullptr, nullptr, nullptr, 256, 256, 0, 0);

    // ---- CLS average ----
    cls_reduce_kernel<<<dim3(8, 4), 256>>>(x, clsp);
    cls_bcast_kernel<<<dim3(8, 4), 256>>>(clsp, x);

    // ---- MLP ----
    ln_kernel<<<NROWS, 256>>>(x, mln_g, mln_b, xn, 0);
    mmagemm<<<dim3(8, NROWS/128), 256, MMA_SMEM>>>(xn, wt+O_W1,
        b1, nullptr, nullptr, nullptr, nullptr, nullptr, nullptr, h, 1024, 256, 1, 0);
    mmagemm<<<dim3(2, NROWS/128), 256, MMA_SMEM>>>(h, wt+O_W2,
        b2, nullptr, nullptr, x, out, nullptr, nullptr, nullptr, 256, 1024, 0, 0);
}